// round 2
// baseline (speedup 1.0000x reference)
#include <cuda_runtime.h>

#define BB   32
#define CC   512
#define HWL  448
#define NH   8
#define DK   64
#define NQC  229376
#define SCL  0.125f
#define BHD  (BB*NH*HWL*DK)       // 7340032

__device__ float g_q [BHD];
__device__ float g_k [BHD];
__device__ float g_v [BHD];
__device__ float g_rp[7*BHD];     // per-j-block partial A*V
__device__ float g_r [BB*HWL*CC];

typedef unsigned long long ull;

__device__ __forceinline__ ull pk2(float x, float y) {
    ull r; asm("mov.b64 %0,{%1,%2};" : "=l"(r) : "f"(x), "f"(y)); return r;
}
__device__ __forceinline__ void up2(ull v, float& x, float& y) {
    asm("mov.b64 {%0,%1},%2;" : "=f"(x), "=f"(y) : "l"(v));
}
__device__ __forceinline__ void fma2(ull& d, ull a, ull b) {
    asm("fma.rn.f32x2 %0,%1,%2,%0;" : "+l"(d) : "l"(a), "l"(b));
}

// ================= K1: q projection (all 32 batches per weight load) =========
__global__ void __launch_bounds__(256) qproj_kernel(const float* __restrict__ s,
                                                    const float* __restrict__ Wq,
                                                    const float* __restrict__ bq) {
    extern __shared__ float st[];                 // [c][b] = [512][32]
    int tid = threadIdx.x;
    for (int idx = tid; idx < BB*CC; idx += 256) {
        int b = idx & 31, c = idx >> 5;
        st[c*32 + b] = s[b*CC + c];
    }
    __syncthreads();
    int j = blockIdx.x * 256 + tid;
    ull acc[16];
#pragma unroll
    for (int p = 0; p < 16; ++p) acc[p] = 0ull;
    const float* wp = Wq + j;
#pragma unroll 2
    for (int c = 0; c < CC; ++c) {
        float w = __ldg(wp + (size_t)c * NQC);
        ull w2 = pk2(w, w);
        const ulonglong2* sp = (const ulonglong2*)(st + c*32);
#pragma unroll
        for (int q = 0; q < 8; ++q) {
            ulonglong2 sv = sp[q];
            fma2(acc[2*q],   sv.x, w2);
            fma2(acc[2*q+1], sv.y, w2);
        }
    }
    float bias = bq[j];
    int i = j >> 9, hd = j & 511, h = hd >> 6, d = hd & 63;
    float* dst = g_q + ((size_t)(h*HWL + i))*DK + d;
#pragma unroll
    for (int p = 0; p < 16; ++p) {
        float x0, x1; up2(acc[p], x0, x1);
        dst[(size_t)(2*p  )*BHD/BB] = x0 + bias;
        dst[(size_t)(2*p+1)*BHD/BB] = x1 + bias;
    }
}

// ================= K2: kv projection (128x128 tile, 8x8/thread, f32x2) =======
__global__ void __launch_bounds__(256) kvproj_kernel(const float* __restrict__ x,
                                                     const float* __restrict__ Wkv,
                                                     const float* __restrict__ bkv) {
    __shared__ float As[8][128];
    __shared__ float Bs[8][128];
    int tid = threadIdx.x;
    int bn = blockIdx.x, bm = blockIdx.y;
    int tx = tid & 15, ty = tid >> 4;
    ull acc[8][4];
#pragma unroll
    for (int a = 0; a < 8; ++a)
#pragma unroll
        for (int b = 0; b < 4; ++b) acc[a][b] = 0ull;

    int la_k = tid >> 5, la_m = (tid & 31) * 4;
    int m4 = bm*128 + la_m;
    int ab = m4 / HWL, at = m4 % HWL;
    const float* Ap = x + ((size_t)ab*CC)*HWL + at;
    const float* Bp = Wkv + (size_t)la_k*1024 + bn*128 + (tid & 31)*4;

    for (int k0 = 0; k0 < CC; k0 += 8) {
        float4 av = *(const float4*)(Ap + (size_t)(k0 + la_k)*HWL);
        float4 bv = *(const float4*)(Bp + (size_t)k0*1024);
        __syncthreads();
        *(float4*)&As[la_k][la_m] = av;
        *(float4*)&Bs[la_k][(tid & 31)*4] = bv;
        __syncthreads();
#pragma unroll
        for (int kk = 0; kk < 8; ++kk) {
            float4 a0 = *(const float4*)&As[kk][ty*4];
            float4 a1 = *(const float4*)&As[kk][64 + ty*4];
            ulonglong2 bA = *(const ulonglong2*)&Bs[kk][tx*4];
            ulonglong2 bB = *(const ulonglong2*)&Bs[kk][64 + tx*4];
            float am[8] = {a0.x,a0.y,a0.z,a0.w,a1.x,a1.y,a1.z,a1.w};
#pragma unroll
            for (int mi = 0; mi < 8; ++mi) {
                ull a2 = pk2(am[mi], am[mi]);
                fma2(acc[mi][0], a2, bA.x);
                fma2(acc[mi][1], a2, bA.y);
                fma2(acc[mi][2], a2, bB.x);
                fma2(acc[mi][3], a2, bB.y);
            }
        }
    }
    int h = bn;
    float4 bk4 = *(const float4*)&bkv[h*128 + tx*4];
    float4 bv4 = *(const float4*)&bkv[h*128 + 64 + tx*4];
#pragma unroll
    for (int mh = 0; mh < 2; ++mh)
#pragma unroll
    for (int mi = 0; mi < 4; ++mi) {
        int m = bm*128 + mh*64 + ty*4 + mi;
        int b = m / HWL, t = m % HWL;
        size_t off = ((size_t)((b*NH + h)*HWL + t))*DK + tx*4;
        int ai = mh*4 + mi;
        float k0v,k1v,k2v,k3v,v0,v1,v2,v3;
        up2(acc[ai][0],k0v,k1v); up2(acc[ai][1],k2v,k3v);
        up2(acc[ai][2],v0,v1);   up2(acc[ai][3],v2,v3);
        *(float4*)(g_k + off) = make_float4(k0v+bk4.x,k1v+bk4.y,k2v+bk4.z,k3v+bk4.w);
        *(float4*)(g_v + off) = make_float4(v0+bv4.x, v1+bv4.y, v2+bv4.z, v3+bv4.w);
    }
}

// ================= K3: fused attention per (b,h,64-j-block) ==================
#define LST 452
#define ATTN_SMEM ((64*68*3 + 64*LST + 64) * 4)

__global__ void __launch_bounds__(256) attn_kernel() {
    extern __shared__ float sm[];
    float* Kst = sm;                  // [d][jj] 64x68, pre-scaled
    float* Qst = Kst + 64*68;         // [d][ii] 64x68
    float* Vs  = Qst + 64*68;         // [jj][d] 64x68, pre-divided
    float* Lsm = Vs  + 64*68;         // [jj][i] 64x452
    float* inv = Lsm + 64*LST;

    int tid = threadIdx.x;
    int jb = blockIdx.x, bh = blockIdx.y;
    int j0 = jb*64;
    const float* Kg = g_k + (size_t)bh*HWL*DK;
    const float* Qg = g_q + (size_t)bh*HWL*DK;
    const float* Vg = g_v + (size_t)bh*HWL*DK;
    int tx = tid & 15, ty = tid >> 4;

    for (int idx = tid; idx < 4096; idx += 256) {
        int d = idx & 63, jj = idx >> 6;
        Kst[d*68 + jj] = Kg[(size_t)(j0 + jj)*DK + d] * SCL;
    }
    // phase 1: logits
    for (int it = 0; it < 7; ++it) {
        int i0 = it*64;
        __syncthreads();
        for (int idx = tid; idx < 4096; idx += 256) {
            int d = idx & 63, ii = idx >> 6;
            Qst[d*68 + ii] = Qg[(size_t)(i0 + ii)*DK + d];
        }
        __syncthreads();
        ull c[4][2];
#pragma unroll
        for (int a = 0; a < 4; ++a) { c[a][0] = 0ull; c[a][1] = 0ull; }
#pragma unroll 8
        for (int d = 0; d < 64; ++d) {
            float4 a = *(const float4*)&Kst[d*68 + ty*4];
            ulonglong2 bq = *(const ulonglong2*)&Qst[d*68 + tx*4];
            float am[4] = {a.x,a.y,a.z,a.w};
#pragma unroll
            for (int jr = 0; jr < 4; ++jr) {
                ull a2 = pk2(am[jr], am[jr]);
                fma2(c[jr][0], a2, bq.x);
                fma2(c[jr][1], a2, bq.y);
            }
        }
#pragma unroll
        for (int jr = 0; jr < 4; ++jr) {
            ull* lp = (ull*)&Lsm[(ty*4 + jr)*LST + i0 + tx*4];
            lp[0] = c[jr][0]; lp[1] = c[jr][1];
        }
    }
    __syncthreads();
    // phase 2: softmax over i per j-row (4 threads/row)
    {
        int row = tid >> 2, q = tid & 3;
        float* Lr = Lsm + row*LST;
        float mx = -1e30f;
        for (int ii = q*112; ii < q*112 + 112; ++ii) mx = fmaxf(mx, Lr[ii]);
        mx = fmaxf(mx, __shfl_xor_sync(0xffffffffu, mx, 1));
        mx = fmaxf(mx, __shfl_xor_sync(0xffffffffu, mx, 2));
        float ssum = 0.f;
        for (int ii = q*112; ii < q*112 + 112; ++ii) {
            float e = __expf(Lr[ii] - mx);
            Lr[ii] = e; ssum += e;
        }
        ssum += __shfl_xor_sync(0xffffffffu, ssum, 1);
        ssum += __shfl_xor_sync(0xffffffffu, ssum, 2);
        if (q == 0) inv[row] = 1.0f / ssum;
    }
    __syncthreads();
    for (int idx = tid; idx < 4096; idx += 256) {
        int d = idx & 63, jj = idx >> 6;
        Vs[jj*68 + d] = Vg[(size_t)(j0 + jj)*DK + d] * inv[jj];
    }
    __syncthreads();
    // phase 3: partial R = A^T V
    float* rp = g_rp + ((size_t)(jb*256 + bh))*HWL*DK;
    for (int it = 0; it < 7; ++it) {
        int i0 = it*64;
        ull acc[4][2];
#pragma unroll
        for (int a = 0; a < 4; ++a) { acc[a][0] = 0ull; acc[a][1] = 0ull; }
#pragma unroll 8
        for (int j = 0; j < 64; ++j) {
            float4 a = *(const float4*)&Lsm[j*LST + i0 + ty*4];
            ulonglong2 bv = *(const ulonglong2*)&Vs[j*68 + tx*4];
            float am[4] = {a.x,a.y,a.z,a.w};
#pragma unroll
            for (int ii = 0; ii < 4; ++ii) {
                ull a2 = pk2(am[ii], am[ii]);
                fma2(acc[ii][0], a2, bv.x);
                fma2(acc[ii][1], a2, bv.y);
            }
        }
#pragma unroll
        for (int ii = 0; ii < 4; ++ii) {
            int i = i0 + ty*4 + ii;
            ulonglong2* dst = (ulonglong2*)(rp + (size_t)i*DK + tx*4);
            *dst = make_ulonglong2(acc[ii][0], acc[ii][1]);
        }
    }
}

// ================= K4: reduce 7 j-block partials -> g_r[b][i][h*64+d] ========
__global__ void __launch_bounds__(256) reduce_kernel() {
    int idx = blockIdx.x*256 + threadIdx.x;
    int hd = idx & 511, bi = idx >> 9;
    int i = bi % HWL, b = bi / HWL;
    size_t src = ((size_t)((b*NH + (hd>>6))*HWL + i))*DK + (hd & 63);
    float sum = 0.f;
#pragma unroll
    for (int jb = 0; jb < 7; ++jb) sum += g_rp[(size_t)jb*BHD + src];
    g_r[idx] = sum;
}

// ================= K5: out projection + residual, output [b][c][t] ===========
__global__ void __launch_bounds__(256) outproj_kernel(const float* __restrict__ x,
                                                      const float* __restrict__ Wo,
                                                      const float* __restrict__ bo,
                                                      float* __restrict__ out) {
    __shared__ float As[8][128];   // [kk][c]
    __shared__ float Bs[8][128];   // [kk][n]
    int tid = threadIdx.x;
    int bn = blockIdx.x, bm = blockIdx.y;
    int tx = tid & 15, ty = tid >> 4;
    ull acc[8][4];
#pragma unroll
    for (int a = 0; a < 8; ++a)
#pragma unroll
        for (int b = 0; b < 4; ++b) acc[a][b] = 0ull;

    int la_k = tid >> 5, la_c = (tid & 31)*4;
    int nl = tid & 127, kq = (tid >> 7)*4;
    int ng = bn*128 + nl;

    for (int k0 = 0; k0 < CC; k0 += 8) {
        float4 av = *(const float4*)(Wo + (size_t)(k0 + la_k)*CC + bm*128 + la_c);
        float4 bvv = *(const float4*)(g_r + (size_t)ng*CC + k0 + kq);
        __syncthreads();
        *(float4*)&As[la_k][la_c] = av;
        Bs[kq  ][nl] = bvv.x; Bs[kq+1][nl] = bvv.y;
        Bs[kq+2][nl] = bvv.z; Bs[kq+3][nl] = bvv.w;
        __syncthreads();
#pragma unroll
        for (int kk = 0; kk < 8; ++kk) {
            float4 a0 = *(const float4*)&As[kk][ty*4];
            float4 a1 = *(const float4*)&As[kk][64 + ty*4];
            ulonglong2 bA = *(const ulonglong2*)&Bs[kk][tx*4];
            ulonglong2 bB = *(const ulonglong2*)&Bs[kk][64 + tx*4];
            float am[8] = {a0.x,a0.y,a0.z,a0.w,a1.x,a1.y,a1.z,a1.w};
#pragma unroll
            for (int mi = 0; mi < 8; ++mi) {
                ull a2 = pk2(am[mi], am[mi]);
                fma2(acc[mi][0], a2, bA.x);
                fma2(acc[mi][1], a2, bA.y);
                fma2(acc[mi][2], a2, bB.x);
                fma2(acc[mi][3], a2, bB.y);
            }
        }
    }
#pragma unroll
    for (int mh = 0; mh < 2; ++mh)
#pragma unroll
    for (int mi = 0; mi < 4; ++mi) {
        int cgl = bm*128 + mh*64 + ty*4 + mi;
        int ai = mh*4 + mi;
        float bias = bo[cgl];
#pragma unroll
        for (int half = 0; half < 2; ++half) {
            int n = bn*128 + half*64 + tx*4;
            int b = n / HWL, t = n % HWL;
            size_t o = (size_t)b*CC*HWL + (size_t)cgl*HWL + t;
            float4 xr = *(const float4*)(x + o);
            float r0,r1,r2,r3;
            up2(acc[ai][2*half],   r0, r1);
            up2(acc[ai][2*half+1], r2, r3);
            *(float4*)(out + o) = make_float4(r0+bias+xr.x, r1+bias+xr.y,
                                              r2+bias+xr.z, r3+bias+xr.w);
        }
    }
}

extern "C" void kernel_launch(void* const* d_in, const int* in_sizes, int n_in,
                              void* d_out, int out_size) {
    const float* x   = (const float*)d_in[0];
    const float* s   = (const float*)d_in[1];
    const float* Wkv = (const float*)d_in[2];
    const float* bkv = (const float*)d_in[3];
    const float* Wq  = (const float*)d_in[4];
    const float* bq  = (const float*)d_in[5];
    const float* Wo  = (const float*)d_in[6];
    const float* bo  = (const float*)d_in[7];
    float* out = (float*)d_out;

    cudaFuncSetAttribute(qproj_kernel, cudaFuncAttributeMaxDynamicSharedMemorySize, 65536);
    cudaFuncSetAttribute(attn_kernel,  cudaFuncAttributeMaxDynamicSharedMemorySize, ATTN_SMEM);

    qproj_kernel<<<NQC/256, 256, 65536>>>(s, Wq, bq);
    kvproj_kernel<<<dim3(8, 112), 256>>>(x, Wkv, bkv);
    attn_kernel<<<dim3(7, 256), 256, ATTN_SMEM>>>();
    reduce_kernel<<<BB*HWL*CC/256, 256>>>();
    outproj_kernel<<<dim3(112, 4), 256>>>(x, Wo, bo, out);
}

// round 3
// speedup vs baseline: 2.3177x; 2.3177x over previous
#include <cuda_runtime.h>

#define BB   32
#define CC   512
#define HWL  448
#define NH   8
#define DK   64
#define NQC  229376
#define SCL  0.125f
#define BHD  (BB*NH*HWL*DK)

__device__ float g_q [BHD];
__device__ float g_k [BHD];
__device__ float g_v [BHD];
__device__ float g_rp[7*BHD];
__device__ float g_r [BB*HWL*CC];

// ---------------- tf32 mma helpers ----------------
__device__ __forceinline__ unsigned tf32c(float f) {
    unsigned u; asm("cvt.rna.tf32.f32 %0,%1;" : "=r"(u) : "f"(f)); return u;
}
__device__ __forceinline__ void mma8(float* c, const unsigned* a, const unsigned* b) {
    asm("mma.sync.aligned.m16n8k8.row.col.f32.tf32.tf32.f32 "
        "{%0,%1,%2,%3},{%4,%5,%6,%7},{%8,%9},{%0,%1,%2,%3};"
        : "+f"(c[0]), "+f"(c[1]), "+f"(c[2]), "+f"(c[3])
        : "r"(a[0]), "r"(a[1]), "r"(a[2]), "r"(a[3]), "r"(b[0]), "r"(b[1]));
}
__device__ __forceinline__ uint4 tf4(float4 v) {
    return make_uint4(tf32c(v.x), tf32c(v.y), tf32c(v.z), tf32c(v.w));
}

// ================= K1: q projection (tf32 mma, weight-streaming) =============
// M=32 (batch), K=512, N=229376. CTA: N-tile 256. As[k][b] pad 40, Bs[k][n] pad 264.
#define QP_SMEM ((512*40 + 64*264)*4)
__global__ void __launch_bounds__(256) qproj_kernel(const float* __restrict__ s,
                                                    const float* __restrict__ Wq,
                                                    const float* __restrict__ bq) {
    extern __shared__ unsigned smu[];
    unsigned* As = smu;            // [512][40]
    unsigned* Bs = As + 512*40;    // [64][264]
    int tid = threadIdx.x;
    int n0 = blockIdx.x * 256;
    int wid = tid >> 5, lane = tid & 31, g = lane >> 2, q = lane & 3;
    int nb = wid * 32;

    for (int idx = tid; idx < BB*CC; idx += 256) {
        int b = idx >> 9, c = idx & 511;
        As[c*40 + b] = tf32c(s[idx]);
    }

    float acc[2][4][4];
#pragma unroll
    for (int mt = 0; mt < 2; ++mt)
#pragma unroll
    for (int nt = 0; nt < 4; ++nt)
#pragma unroll
    for (int r = 0; r < 4; ++r) acc[mt][nt][r] = 0.f;

    for (int k0 = 0; k0 < CC; k0 += 64) {
        float4 rv[16];
#pragma unroll
        for (int r = 0; r < 16; ++r) {
            int fid = tid + r*256;
            int kk = fid >> 6, c4 = (fid & 63)*4;
            rv[r] = *(const float4*)(Wq + (size_t)(k0 + kk)*NQC + n0 + c4);
        }
        __syncthreads();
#pragma unroll
        for (int r = 0; r < 16; ++r) {
            int fid = tid + r*256;
            int kk = fid >> 6, c4 = (fid & 63)*4;
            *(uint4*)&Bs[kk*264 + c4] = tf4(rv[r]);
        }
        __syncthreads();
        for (int kk8 = 0; kk8 < 8; ++kk8) {
            int kA = k0 + kk8*8;
            unsigned a[2][4], b[4][2];
#pragma unroll
            for (int mt = 0; mt < 2; ++mt) {
                a[mt][0] = As[(kA+q)*40   + mt*16 + g];
                a[mt][1] = As[(kA+q)*40   + mt*16 + g + 8];
                a[mt][2] = As[(kA+q+4)*40 + mt*16 + g];
                a[mt][3] = As[(kA+q+4)*40 + mt*16 + g + 8];
            }
#pragma unroll
            for (int nt = 0; nt < 4; ++nt) {
                b[nt][0] = Bs[(kk8*8+q)*264   + nb + nt*8 + g];
                b[nt][1] = Bs[(kk8*8+q+4)*264 + nb + nt*8 + g];
            }
#pragma unroll
            for (int mt = 0; mt < 2; ++mt)
#pragma unroll
            for (int nt = 0; nt < 4; ++nt) mma8(acc[mt][nt], a[mt], b[nt]);
        }
    }
#pragma unroll
    for (int nt = 0; nt < 4; ++nt) {
        int j = n0 + nb + nt*8 + 2*q;
        int i = j >> 9, hd = j & 511, h = hd >> 6, d = hd & 63;
        float b0f = bq[j], b1f = bq[j+1];
#pragma unroll
        for (int mt = 0; mt < 2; ++mt) {
            int br = mt*16 + g;
            float* d0 = g_q + ((size_t)((br*NH + h)*HWL + i))*DK + d;
            float* d1 = g_q + ((size_t)(((br+8)*NH + h)*HWL + i))*DK + d;
            *(float2*)d0 = make_float2(acc[mt][nt][0] + b0f, acc[mt][nt][1] + b1f);
            *(float2*)d1 = make_float2(acc[mt][nt][2] + b0f, acc[mt][nt][3] + b1f);
        }
    }
}

// ================= K2: kv projection (tf32 mma) ==============================
// M=14336, K=512, N=1024. CTA 128x128; warps 2(M)x4(N), warp 64x32.
__global__ void __launch_bounds__(256) kvproj_kernel(const float* __restrict__ x,
                                                     const float* __restrict__ Wkv,
                                                     const float* __restrict__ bkv) {
    __shared__ unsigned As[32*136];   // [k][m]
    __shared__ unsigned Bs[32*136];   // [k][n]
    int tid = threadIdx.x;
    int bn = blockIdx.x, bm = blockIdx.y;
    int wid = tid >> 5, lane = tid & 31, g = lane >> 2, q = lane & 3;
    int mbw = (wid & 1)*64, nbw = (wid >> 1)*32;

    float acc[4][4][4];
#pragma unroll
    for (int mt = 0; mt < 4; ++mt)
#pragma unroll
    for (int nt = 0; nt < 4; ++nt)
#pragma unroll
    for (int r = 0; r < 4; ++r) acc[mt][nt][r] = 0.f;

    for (int k0 = 0; k0 < CC; k0 += 32) {
        float4 ra[4], rb[4];
#pragma unroll
        for (int r = 0; r < 4; ++r) {
            int fid = tid + r*256;
            int kk = fid >> 5, m4 = (fid & 31)*4;
            int m = bm*128 + m4;
            int ab = m / HWL, at = m % HWL;
            ra[r] = *(const float4*)(x + ((size_t)(ab*CC + k0 + kk))*HWL + at);
            rb[r] = *(const float4*)(Wkv + (size_t)(k0 + kk)*1024 + bn*128 + m4);
        }
        __syncthreads();
#pragma unroll
        for (int r = 0; r < 4; ++r) {
            int fid = tid + r*256;
            int kk = fid >> 5, m4 = (fid & 31)*4;
            *(uint4*)&As[kk*136 + m4] = tf4(ra[r]);
            *(uint4*)&Bs[kk*136 + m4] = tf4(rb[r]);
        }
        __syncthreads();
#pragma unroll
        for (int kk8 = 0; kk8 < 4; ++kk8) {
            unsigned a[4][4], b[4][2];
#pragma unroll
            for (int mt = 0; mt < 4; ++mt) {
                a[mt][0] = As[(kk8*8+q)*136   + mbw + mt*16 + g];
                a[mt][1] = As[(kk8*8+q)*136   + mbw + mt*16 + g + 8];
                a[mt][2] = As[(kk8*8+q+4)*136 + mbw + mt*16 + g];
                a[mt][3] = As[(kk8*8+q+4)*136 + mbw + mt*16 + g + 8];
            }
#pragma unroll
            for (int nt = 0; nt < 4; ++nt) {
                b[nt][0] = Bs[(kk8*8+q)*136   + nbw + nt*8 + g];
                b[nt][1] = Bs[(kk8*8+q+4)*136 + nbw + nt*8 + g];
            }
#pragma unroll
            for (int mt = 0; mt < 4; ++mt)
#pragma unroll
            for (int nt = 0; nt < 4; ++nt) mma8(acc[mt][nt], a[mt], b[nt]);
        }
    }
#pragma unroll
    for (int nt = 0; nt < 4; ++nt) {
        int n = nbw + nt*8 + 2*q;
        float b0f = bkv[bn*128 + n], b1f = bkv[bn*128 + n + 1];
        int d = n & 63;
        float* base = (n < 64) ? g_k : g_v;
#pragma unroll
        for (int mt = 0; mt < 4; ++mt) {
            int m = bm*128 + mbw + mt*16 + g;
            int b0 = m / HWL, t0 = m % HWL;
            int m1 = m + 8;
            int b1 = m1 / HWL, t1 = m1 % HWL;
            *(float2*)(base + ((size_t)((b0*NH + bn)*HWL + t0))*DK + d) =
                make_float2(acc[mt][nt][0] + b0f, acc[mt][nt][1] + b1f);
            *(float2*)(base + ((size_t)((b1*NH + bn)*HWL + t1))*DK + d) =
                make_float2(acc[mt][nt][2] + b0f, acc[mt][nt][3] + b1f);
        }
    }
}

// ================= K3: fused attention (tf32 mma) ============================
#define LST 456
#define ATTN_SMEM ((64*72 + 224*72 + 64*72 + 64*LST + 80)*4)
__global__ void __launch_bounds__(256) attn_kernel() {
    extern __shared__ unsigned smu[];
    unsigned* Ks = smu;                   // [j][d] pad 72, pre-scaled
    unsigned* Qs = Ks + 64*72;            // [i][d] pad 72 (224 rows)
    unsigned* Vs = Qs + 224*72;           // [j][d] pad 72, pre-divided
    float*    Lsm = (float*)(Vs + 64*72); // [j][i] pad 456 (tf32 bits after softmax)
    float*    inv = Lsm + 64*LST;
    unsigned* Lu = (unsigned*)Lsm;

    int tid = threadIdx.x;
    int jb = blockIdx.x, bh = blockIdx.y;
    int j0 = jb*64;
    const float* Kg = g_k + (size_t)bh*HWL*DK;
    const float* Qg = g_q + (size_t)bh*HWL*DK;
    const float* Vg = g_v + (size_t)bh*HWL*DK;
    int wid = tid >> 5, lane = tid & 31, g = lane >> 2, q = lane & 3;

    // K tile (pre-scaled)
#pragma unroll
    for (int r = 0; r < 4; ++r) {
        int fid = tid + r*256;
        int jj = fid >> 4, d4 = (fid & 15)*4;
        float4 v = *(const float4*)(Kg + (size_t)(j0 + jj)*DK + d4);
        v.x *= SCL; v.y *= SCL; v.z *= SCL; v.w *= SCL;
        *(uint4*)&Ks[jj*72 + d4] = tf4(v);
    }
    // ---- phase 1: logits (two i-halves of 224) ----
    int jbw = (wid & 1)*32, ibw = (wid >> 1)*56;
    for (int ih = 0; ih < 2; ++ih) {
        float4 rq[14];
#pragma unroll
        for (int r = 0; r < 14; ++r) {
            int fid = tid + r*256;
            int ii = fid >> 4, d4 = (fid & 15)*4;
            rq[r] = *(const float4*)(Qg + (size_t)(ih*224 + ii)*DK + d4);
        }
        __syncthreads();
#pragma unroll
        for (int r = 0; r < 14; ++r) {
            int fid = tid + r*256;
            int ii = fid >> 4, d4 = (fid & 15)*4;
            *(uint4*)&Qs[ii*72 + d4] = tf4(rq[r]);
        }
        __syncthreads();
        float acc[2][7][4];
#pragma unroll
        for (int mt = 0; mt < 2; ++mt)
#pragma unroll
        for (int nt = 0; nt < 7; ++nt)
#pragma unroll
        for (int r = 0; r < 4; ++r) acc[mt][nt][r] = 0.f;

        for (int kk8 = 0; kk8 < 8; ++kk8) {
            unsigned a[2][4], b[7][2];
#pragma unroll
            for (int mt = 0; mt < 2; ++mt) {
                a[mt][0] = Ks[(jbw + mt*16 + g)*72     + kk8*8 + q];
                a[mt][1] = Ks[(jbw + mt*16 + g + 8)*72 + kk8*8 + q];
                a[mt][2] = Ks[(jbw + mt*16 + g)*72     + kk8*8 + q + 4];
                a[mt][3] = Ks[(jbw + mt*16 + g + 8)*72 + kk8*8 + q + 4];
            }
#pragma unroll
            for (int nt = 0; nt < 7; ++nt) {
                b[nt][0] = Qs[(ibw + nt*8 + g)*72 + kk8*8 + q];
                b[nt][1] = Qs[(ibw + nt*8 + g)*72 + kk8*8 + q + 4];
            }
#pragma unroll
            for (int mt = 0; mt < 2; ++mt)
#pragma unroll
            for (int nt = 0; nt < 7; ++nt) mma8(acc[mt][nt], a[mt], b[nt]);
        }
#pragma unroll
        for (int nt = 0; nt < 7; ++nt) {
            int i = ih*224 + ibw + nt*8 + 2*q;
#pragma unroll
            for (int mt = 0; mt < 2; ++mt) {
                int jr = jbw + mt*16 + g;
                *(float2*)&Lsm[jr*LST + i]     = make_float2(acc[mt][nt][0], acc[mt][nt][1]);
                *(float2*)&Lsm[(jr+8)*LST + i] = make_float2(acc[mt][nt][2], acc[mt][nt][3]);
            }
        }
        __syncthreads();
    }
    // ---- phase 2: softmax over i per j-row; store tf32 bits in place ----
    {
        int row = tid >> 2, qq = tid & 3;
        float* Lr = Lsm + row*LST;
        float mx = -1e30f;
        for (int ii = qq*112; ii < qq*112 + 112; ++ii) mx = fmaxf(mx, Lr[ii]);
        mx = fmaxf(mx, __shfl_xor_sync(0xffffffffu, mx, 1));
        mx = fmaxf(mx, __shfl_xor_sync(0xffffffffu, mx, 2));
        float ssum = 0.f;
        for (int ii = qq*112; ii < qq*112 + 112; ++ii) {
            float e = __expf(Lr[ii] - mx);
            ssum += e;
            Lu[row*LST + ii] = tf32c(e);
        }
        ssum += __shfl_xor_sync(0xffffffffu, ssum, 1);
        ssum += __shfl_xor_sync(0xffffffffu, ssum, 2);
        if (qq == 0) inv[row] = 1.0f / ssum;
    }
    __syncthreads();
    // V tile scaled by 1/rowsum
#pragma unroll
    for (int r = 0; r < 4; ++r) {
        int fid = tid + r*256;
        int jj = fid >> 4, d4 = (fid & 15)*4;
        float4 v = *(const float4*)(Vg + (size_t)(j0 + jj)*DK + d4);
        float iv = inv[jj];
        v.x *= iv; v.y *= iv; v.z *= iv; v.w *= iv;
        *(uint4*)&Vs[jj*72 + d4] = tf4(v);
    }
    __syncthreads();
    // ---- phase 3: partial R = P^T V ----
    float* rp = g_rp + ((size_t)(jb*256 + bh))*HWL*DK;
    int ibw3 = (wid & 3)*112, dbw = (wid >> 2)*32;
    float acc[7][4][4];
#pragma unroll
    for (int mt = 0; mt < 7; ++mt)
#pragma unroll
    for (int nt = 0; nt < 4; ++nt)
#pragma unroll
    for (int r = 0; r < 4; ++r) acc[mt][nt][r] = 0.f;

    for (int kk8 = 0; kk8 < 8; ++kk8) {
        unsigned a[7][4], b[4][2];
#pragma unroll
        for (int mt = 0; mt < 7; ++mt) {
            a[mt][0] = Lu[(kk8*8+q)*LST   + ibw3 + mt*16 + g];
            a[mt][1] = Lu[(kk8*8+q)*LST   + ibw3 + mt*16 + g + 8];
            a[mt][2] = Lu[(kk8*8+q+4)*LST + ibw3 + mt*16 + g];
            a[mt][3] = Lu[(kk8*8+q+4)*LST + ibw3 + mt*16 + g + 8];
        }
#pragma unroll
        for (int nt = 0; nt < 4; ++nt) {
            b[nt][0] = Vs[(kk8*8+q)*72   + dbw + nt*8 + g];
            b[nt][1] = Vs[(kk8*8+q+4)*72 + dbw + nt*8 + g];
        }
#pragma unroll
        for (int mt = 0; mt < 7; ++mt)
#pragma unroll
        for (int nt = 0; nt < 4; ++nt) mma8(acc[mt][nt], a[mt], b[nt]);
    }
#pragma unroll
    for (int nt = 0; nt < 4; ++nt) {
        int d = dbw + nt*8 + 2*q;
#pragma unroll
        for (int mt = 0; mt < 7; ++mt) {
            int i = ibw3 + mt*16 + g;
            *(float2*)(rp + (size_t)i*DK + d)     = make_float2(acc[mt][nt][0], acc[mt][nt][1]);
            *(float2*)(rp + (size_t)(i+8)*DK + d) = make_float2(acc[mt][nt][2], acc[mt][nt][3]);
        }
    }
}

// ================= K4: reduce 7 j-block partials =============================
__global__ void __launch_bounds__(256) reduce_kernel() {
    int idx = blockIdx.x*256 + threadIdx.x;
    int hd = idx & 511, bi = idx >> 9;
    int i = bi % HWL, b = bi / HWL;
    size_t src = ((size_t)((b*NH + (hd >> 6))*HWL + i))*DK + (hd & 63);
    float sum = 0.f;
#pragma unroll
    for (int jb = 0; jb < 7; ++jb) sum += g_rp[(size_t)jb*BHD + src];
    g_r[idx] = sum;
}

// ================= K5: out projection + residual (tf32 mma) ==================
// M=c (512), N=m (14336), K=512. CTA 128x128; warps 2(c)x4(n).
__global__ void __launch_bounds__(256) outproj_kernel(const float* __restrict__ x,
                                                      const float* __restrict__ Wo,
                                                      const float* __restrict__ bo,
                                                      float* __restrict__ out) {
    __shared__ unsigned As[32*136];   // [k][c]
    __shared__ unsigned Bs[128*36];   // [n][k]
    int tid = threadIdx.x;
    int bn = blockIdx.x, bm = blockIdx.y;
    int wid = tid >> 5, lane = tid & 31, g = lane >> 2, q = lane & 3;
    int cbw = (wid & 1)*64, nbw = (wid >> 1)*32;

    float acc[4][4][4];
#pragma unroll
    for (int mt = 0; mt < 4; ++mt)
#pragma unroll
    for (int nt = 0; nt < 4; ++nt)
#pragma unroll
    for (int r = 0; r < 4; ++r) acc[mt][nt][r] = 0.f;

    for (int k0 = 0; k0 < CC; k0 += 32) {
        float4 ra[4], rb[4];
#pragma unroll
        for (int r = 0; r < 4; ++r) {
            int fid = tid + r*256;
            int kk = fid >> 5, c4 = (fid & 31)*4;
            ra[r] = *(const float4*)(Wo + (size_t)(k0 + kk)*CC + bm*128 + c4);
            int n = fid >> 3, k4 = (fid & 7)*4;
            rb[r] = *(const float4*)(g_r + (size_t)(bn*128 + n)*CC + k0 + k4);
        }
        __syncthreads();
#pragma unroll
        for (int r = 0; r < 4; ++r) {
            int fid = tid + r*256;
            int kk = fid >> 5, c4 = (fid & 31)*4;
            *(uint4*)&As[kk*136 + c4] = tf4(ra[r]);
            int n = fid >> 3, k4 = (fid & 7)*4;
            *(uint4*)&Bs[n*36 + k4] = tf4(rb[r]);
        }
        __syncthreads();
#pragma unroll
        for (int kk8 = 0; kk8 < 4; ++kk8) {
            unsigned a[4][4], b[4][2];
#pragma unroll
            for (int mt = 0; mt < 4; ++mt) {
                a[mt][0] = As[(kk8*8+q)*136   + cbw + mt*16 + g];
                a[mt][1] = As[(kk8*8+q)*136   + cbw + mt*16 + g + 8];
                a[mt][2] = As[(kk8*8+q+4)*136 + cbw + mt*16 + g];
                a[mt][3] = As[(kk8*8+q+4)*136 + cbw + mt*16 + g + 8];
            }
#pragma unroll
            for (int nt = 0; nt < 4; ++nt) {
                b[nt][0] = Bs[(nbw + nt*8 + g)*36 + kk8*8 + q];
                b[nt][1] = Bs[(nbw + nt*8 + g)*36 + kk8*8 + q + 4];
            }
#pragma unroll
            for (int mt = 0; mt < 4; ++mt)
#pragma unroll
            for (int nt = 0; nt < 4; ++nt) mma8(acc[mt][nt], a[mt], b[nt]);
        }
    }
#pragma unroll
    for (int nt = 0; nt < 4; ++nt) {
        int m = bn*128 + nbw + nt*8 + 2*q;
        int b = m / HWL, t = m % HWL;
#pragma unroll
        for (int mt = 0; mt < 4; ++mt) {
            int c0 = bm*128 + cbw + mt*16 + g;
            float bias0 = bo[c0], bias1 = bo[c0 + 8];
            size_t o0 = (size_t)b*CC*HWL + (size_t)c0*HWL + t;
            size_t o1 = o0 + (size_t)8*HWL;
            float2 x0 = *(const float2*)(x + o0);
            float2 x1 = *(const float2*)(x + o1);
            *(float2*)(out + o0) = make_float2(acc[mt][nt][0] + bias0 + x0.x,
                                               acc[mt][nt][1] + bias0 + x0.y);
            *(float2*)(out + o1) = make_float2(acc[mt][nt][2] + bias1 + x1.x,
                                               acc[mt][nt][3] + bias1 + x1.y);
        }
    }
}

extern "C" void kernel_launch(void* const* d_in, const int* in_sizes, int n_in,
                              void* d_out, int out_size) {
    const float* x   = (const float*)d_in[0];
    const float* s   = (const float*)d_in[1];
    const float* Wkv = (const float*)d_in[2];
    const float* bkv = (const float*)d_in[3];
    const float* Wq  = (const float*)d_in[4];
    const float* bq  = (const float*)d_in[5];
    const float* Wo  = (const float*)d_in[6];
    const float* bo  = (const float*)d_in[7];
    float* out = (float*)d_out;

    cudaFuncSetAttribute(qproj_kernel, cudaFuncAttributeMaxDynamicSharedMemorySize, QP_SMEM);
    cudaFuncSetAttribute(attn_kernel,  cudaFuncAttributeMaxDynamicSharedMemorySize, ATTN_SMEM);

    qproj_kernel<<<NQC/256, 256, QP_SMEM>>>(s, Wq, bq);
    kvproj_kernel<<<dim3(8, 112), 256>>>(x, Wkv, bkv);
    attn_kernel<<<dim3(7, 256), 256, ATTN_SMEM>>>();
    reduce_kernel<<<BB*HWL*CC/256, 256>>>();
    outproj_kernel<<<dim3(112, 4), 256>>>(x, Wo, bo, out);
}

// round 6
// speedup vs baseline: 3.1021x; 1.3384x over previous
#include <cuda_runtime.h>

#define BB   32
#define CC   512
#define HWL  448
#define NH   8
#define DK   64
#define NQC  229376
#define SCL  0.125f
#define BHD  (BB*NH*HWL*DK)

__device__ float g_q [BHD];
__device__ float g_k [BHD];
__device__ float g_v [BHD];
__device__ float g_r [BB*HWL*CC];

__device__ __forceinline__ unsigned tf32c(float f) {
    unsigned u; asm("cvt.rna.tf32.f32 %0,%1;" : "=r"(u) : "f"(f)); return u;
}
// round-to-nearest for raw fp32 bits feeding tf32 MMA (HW truncates low 13)
__device__ __forceinline__ unsigned rnd(unsigned u) { return u + 0x1000u; }

__device__ __forceinline__ void mma8(float* c, const unsigned* a, const unsigned* b) {
    asm("mma.sync.aligned.m16n8k8.row.col.f32.tf32.tf32.f32 "
        "{%0,%1,%2,%3},{%4,%5,%6,%7},{%8,%9},{%0,%1,%2,%3};"
        : "+f"(c[0]), "+f"(c[1]), "+f"(c[2]), "+f"(c[3])
        : "r"(a[0]), "r"(a[1]), "r"(a[2]), "r"(a[3]), "r"(b[0]), "r"(b[1]));
}
__device__ __forceinline__ void cpa16(void* sm, const void* gm) {
    unsigned sa = (unsigned)__cvta_generic_to_shared(sm);
    asm volatile("cp.async.cg.shared.global [%0],[%1],16;" :: "r"(sa), "l"(gm));
}
#define CP_COMMIT() asm volatile("cp.async.commit_group;")
#define CP_WAIT(n)  asm volatile("cp.async.wait_group %0;" :: "n"(n))

// ================= K1: q projection (double-buffered) ========================
#define QP_SMEM ((512*40 + 2*64*264)*4)
__global__ void __launch_bounds__(256) qproj_kernel(const float* __restrict__ s,
                                                    const float* __restrict__ Wq,
                                                    const float* __restrict__ bq) {
    extern __shared__ unsigned smu[];
    unsigned* As  = smu;             // [512][40] tf32 (rna), [c][b]
    unsigned* Bs0 = As + 512*40;     // 2 x [64][264] raw fp32 bits
    int tid = threadIdx.x;
    int n0 = blockIdx.x * 256;
    int wid = tid >> 5, lane = tid & 31, g = lane >> 2, q = lane & 3;
    int nb = wid * 32;

    for (int idx = tid; idx < BB*CC; idx += 256) {
        int b = idx >> 9, c = idx & 511;
        As[c*40 + b] = tf32c(s[b*CC + c]);
    }
    {
        unsigned* B = Bs0;
#pragma unroll
        for (int r = 0; r < 16; ++r) {
            int fid = r*256 + tid;
            int kk = fid >> 6, ch = (fid & 63)*4;
            cpa16(&B[kk*264 + ch], Wq + (size_t)kk*NQC + n0 + ch);
        }
        CP_COMMIT();
    }
    float acc[2][4][4];
#pragma unroll
    for (int mt = 0; mt < 2; ++mt)
#pragma unroll
    for (int nt = 0; nt < 4; ++nt)
#pragma unroll
    for (int r = 0; r < 4; ++r) acc[mt][nt][r] = 0.f;

    for (int kt = 0; kt < 8; ++kt) {
        if (kt < 7) {
            unsigned* B = Bs0 + ((kt+1)&1)*64*264;
#pragma unroll
            for (int r = 0; r < 16; ++r) {
                int fid = r*256 + tid;
                int kk = fid >> 6, ch = (fid & 63)*4;
                cpa16(&B[kk*264 + ch], Wq + (size_t)((kt+1)*64 + kk)*NQC + n0 + ch);
            }
            CP_COMMIT();
            CP_WAIT(1);
        } else {
            CP_WAIT(0);
        }
        __syncthreads();
        unsigned* Bs = Bs0 + (kt&1)*64*264;
#pragma unroll
        for (int kk8 = 0; kk8 < 8; ++kk8) {
            int kA = kt*64 + kk8*8;
            unsigned a[2][4], b[4][2];
#pragma unroll
            for (int mt = 0; mt < 2; ++mt) {
                a[mt][0] = As[(kA+q)*40   + mt*16 + g];
                a[mt][1] = As[(kA+q)*40   + mt*16 + g + 8];
                a[mt][2] = As[(kA+q+4)*40 + mt*16 + g];
                a[mt][3] = As[(kA+q+4)*40 + mt*16 + g + 8];
            }
#pragma unroll
            for (int nt = 0; nt < 4; ++nt) {
                b[nt][0] = rnd(Bs[(kk8*8+q)*264   + nb + nt*8 + g]);
                b[nt][1] = rnd(Bs[(kk8*8+q+4)*264 + nb + nt*8 + g]);
            }
#pragma unroll
            for (int mt = 0; mt < 2; ++mt)
#pragma unroll
            for (int nt = 0; nt < 4; ++nt) mma8(acc[mt][nt], a[mt], b[nt]);
        }
        __syncthreads();
    }
#pragma unroll
    for (int nt = 0; nt < 4; ++nt) {
        int j = n0 + nb + nt*8 + 2*q;
        int i = j >> 9, hd = j & 511, h = hd >> 6, d = hd & 63;
        float b0f = bq[j], b1f = bq[j+1];
#pragma unroll
        for (int mt = 0; mt < 2; ++mt) {
            int br = mt*16 + g;
            float* d0 = g_q + ((size_t)((br*NH + h)*HWL + i))*DK + d;
            float* d1 = g_q + ((size_t)(((br+8)*NH + h)*HWL + i))*DK + d;
            *(float2*)d0 = make_float2(acc[mt][nt][0] + b0f, acc[mt][nt][1] + b1f);
            *(float2*)d1 = make_float2(acc[mt][nt][2] + b0f, acc[mt][nt][3] + b1f);
        }
    }
}

// ================= K2: kv projection (double-buffered) =======================
#define KV_SMEM (4*32*136*4)
__global__ void __launch_bounds__(256) kvproj_kernel(const float* __restrict__ x,
                                                     const float* __restrict__ Wkv,
                                                     const float* __restrict__ bkv) {
    extern __shared__ unsigned smu[];
    unsigned* As0 = smu;
    unsigned* Bs0 = smu + 2*32*136;
    int tid = threadIdx.x;
    int bn = blockIdx.x, bm = blockIdx.y;
    int wid = tid >> 5, lane = tid & 31, g = lane >> 2, q = lane & 3;
    int mbw = (wid & 1)*64, nbw = (wid >> 1)*32;

    float acc[4][4][4];
#pragma unroll
    for (int mt = 0; mt < 4; ++mt)
#pragma unroll
    for (int nt = 0; nt < 4; ++nt)
#pragma unroll
    for (int r = 0; r < 4; ++r) acc[mt][nt][r] = 0.f;

#define KV_STAGE(kt, buf)                                                       \
    {                                                                           \
        unsigned* A = As0 + (buf)*32*136;                                       \
        unsigned* B = Bs0 + (buf)*32*136;                                       \
        _Pragma("unroll")                                                       \
        for (int r = 0; r < 4; ++r) {                                           \
            int fid = r*256 + tid;                                              \
            int kk = fid >> 5, m4 = (fid & 31)*4;                               \
            int m = bm*128 + m4;                                                \
            int ab = m / HWL, at = m % HWL;                                     \
            cpa16(&A[kk*136 + m4], x + ((size_t)(ab*CC + (kt)*32 + kk))*HWL + at); \
            cpa16(&B[kk*136 + m4], Wkv + (size_t)((kt)*32 + kk)*1024 + bn*128 + m4); \
        }                                                                       \
        CP_COMMIT();                                                            \
    }

    KV_STAGE(0, 0);
    for (int kt = 0; kt < 16; ++kt) {
        if (kt < 15) { KV_STAGE(kt+1, (kt+1)&1); CP_WAIT(1); }
        else         { CP_WAIT(0); }
        __syncthreads();
        unsigned* As = As0 + (kt&1)*32*136;
        unsigned* Bs = Bs0 + (kt&1)*32*136;
#pragma unroll
        for (int kk8 = 0; kk8 < 4; ++kk8) {
            unsigned a[4][4], b[4][2];
#pragma unroll
            for (int mt = 0; mt < 4; ++mt) {
                a[mt][0] = rnd(As[(kk8*8+q)*136   + mbw + mt*16 + g]);
                a[mt][1] = rnd(As[(kk8*8+q)*136   + mbw + mt*16 + g + 8]);
                a[mt][2] = rnd(As[(kk8*8+q+4)*136 + mbw + mt*16 + g]);
                a[mt][3] = rnd(As[(kk8*8+q+4)*136 + mbw + mt*16 + g + 8]);
            }
#pragma unroll
            for (int nt = 0; nt < 4; ++nt) {
                b[nt][0] = rnd(Bs[(kk8*8+q)*136   + nbw + nt*8 + g]);
                b[nt][1] = rnd(Bs[(kk8*8+q+4)*136 + nbw + nt*8 + g]);
            }
#pragma unroll
            for (int mt = 0; mt < 4; ++mt)
#pragma unroll
            for (int nt = 0; nt < 4; ++nt) mma8(acc[mt][nt], a[mt], b[nt]);
        }
        __syncthreads();
    }
#pragma unroll
    for (int nt = 0; nt < 4; ++nt) {
        int n = nbw + nt*8 + 2*q;
        float b0f = bkv[bn*128 + n], b1f = bkv[bn*128 + n + 1];
        int d = n & 63;
        float* base = (n < 64) ? g_k : g_v;
#pragma unroll
        for (int mt = 0; mt < 4; ++mt) {
            int m = bm*128 + mbw + mt*16 + g;
            int b0 = m / HWL, t0 = m % HWL;
            int m1 = m + 8;
            int b1 = m1 / HWL, t1 = m1 % HWL;
            *(float2*)(base + ((size_t)((b0*NH + bn)*HWL + t0))*DK + d) =
                make_float2(acc[mt][nt][0] + b0f, acc[mt][nt][1] + b1f);
            *(float2*)(base + ((size_t)((b1*NH + bn)*HWL + t1))*DK + d) =
                make_float2(acc[mt][nt][2] + b0f, acc[mt][nt][3] + b1f);
        }
    }
}

// ================= K3: merged fused attention per (b,h) ======================
#define LST 456
#define ATTN_SMEM ((64*68 + 224*72 + 64*72 + 64*LST + 64)*4)
__global__ void __launch_bounds__(256) attn_kernel() {
    extern __shared__ unsigned smu[];
    unsigned* Ks = smu;                    // [j][d] stride 68 (raw; SCL folded into softmax)
    unsigned* Qs = Ks + 64*68;             // [i][d] stride 72 (224 rows)
    unsigned* Vs = Qs + 224*72;            // [j][d] stride 72 (tf32, scaled by 1/rowsum)
    float*    Lsm = (float*)(Vs + 64*72);  // [j][i] stride 456
    float*    inv = Lsm + 64*LST;
    unsigned* Lu = (unsigned*)Lsm;

    int tid = threadIdx.x;
    int bh = blockIdx.x;
    const float* Kg = g_k + (size_t)bh*HWL*DK;
    const float* Qg = g_q + (size_t)bh*HWL*DK;
    const float* Vg = g_v + (size_t)bh*HWL*DK;
    int wid = tid >> 5, lane = tid & 31, g = lane >> 2, q = lane & 3;
    int jbw = (wid & 1)*32, ibw = (wid >> 1)*56;
    int ibw3 = (wid & 3)*112, dbw = (wid >> 2)*32;
    int bb = bh >> 3, hh = bh & 7;

    float acc_o[7][4][4];
#pragma unroll
    for (int mt = 0; mt < 7; ++mt)
#pragma unroll
    for (int nt = 0; nt < 4; ++nt)
#pragma unroll
    for (int r = 0; r < 4; ++r) acc_o[mt][nt][r] = 0.f;

    for (int jb = 0; jb < 7; ++jb) {
        int j0 = jb*64;
        // stage K(jb): 64 rows x 16 chunks = 1024 chunks  (FIXED: full DK coverage)
        {
#pragma unroll
            for (int r = 0; r < 4; ++r) {
                int fid = r*256 + tid;
                int jj = fid >> 4, ch = (fid & 15)*4;
                cpa16(&Ks[jj*68 + ch], Kg + (size_t)(j0 + jj)*DK + ch);
            }
            CP_COMMIT();
        }
        // ---- phase 1: logits over two i-halves ----
        for (int ih = 0; ih < 2; ++ih) {
            // stage Q: 224 rows x 16 chunks = 3584 chunks  (FIXED: full DK coverage)
#pragma unroll
            for (int r = 0; r < 14; ++r) {
                int fid = r*256 + tid;
                int ii = fid >> 4, ch = (fid & 15)*4;
                cpa16(&Qs[ii*72 + ch], Qg + (size_t)(ih*224 + ii)*DK + ch);
            }
            CP_COMMIT();
            CP_WAIT(0);
            __syncthreads();

            float a1[2][7][4];
#pragma unroll
            for (int mt = 0; mt < 2; ++mt)
#pragma unroll
            for (int nt = 0; nt < 7; ++nt)
#pragma unroll
            for (int r = 0; r < 4; ++r) a1[mt][nt][r] = 0.f;
#pragma unroll
            for (int kk8 = 0; kk8 < 8; ++kk8) {
                unsigned a[2][4], b[7][2];
#pragma unroll
                for (int mt = 0; mt < 2; ++mt) {
                    a[mt][0] = rnd(Ks[(jbw + mt*16 + g)*68     + kk8*8 + q]);
                    a[mt][1] = rnd(Ks[(jbw + mt*16 + g + 8)*68 + kk8*8 + q]);
                    a[mt][2] = rnd(Ks[(jbw + mt*16 + g)*68     + kk8*8 + q + 4]);
                    a[mt][3] = rnd(Ks[(jbw + mt*16 + g + 8)*68 + kk8*8 + q + 4]);
                }
#pragma unroll
                for (int nt = 0; nt < 7; ++nt) {
                    b[nt][0] = rnd(Qs[(ibw + nt*8 + g)*72 + kk8*8 + q]);
                    b[nt][1] = rnd(Qs[(ibw + nt*8 + g)*72 + kk8*8 + q + 4]);
                }
#pragma unroll
                for (int mt = 0; mt < 2; ++mt)
#pragma unroll
                for (int nt = 0; nt < 7; ++nt) mma8(a1[mt][nt], a[mt], b[nt]);
            }
#pragma unroll
            for (int nt = 0; nt < 7; ++nt) {
                int i = ih*224 + ibw + nt*8 + 2*q;
#pragma unroll
                for (int mt = 0; mt < 2; ++mt) {
                    int jr = jbw + mt*16 + g;
                    *(float2*)&Lsm[jr*LST + i]     = make_float2(a1[mt][nt][0], a1[mt][nt][1]);
                    *(float2*)&Lsm[(jr+8)*LST + i] = make_float2(a1[mt][nt][2], a1[mt][nt][3]);
                }
            }
            __syncthreads();
        }
        // ---- phase 2: softmax over i per j-row (SCL folded), store tf32 ----
        {
            int row = tid >> 2, qq = tid & 3;
            float* Lr = Lsm + row*LST;
            float mx = -1e30f;
            for (int ii = qq*112; ii < qq*112 + 112; ++ii) mx = fmaxf(mx, Lr[ii]);
            mx = fmaxf(mx, __shfl_xor_sync(0xffffffffu, mx, 1));
            mx = fmaxf(mx, __shfl_xor_sync(0xffffffffu, mx, 2));
            float ssum = 0.f;
            for (int ii = qq*112; ii < qq*112 + 112; ++ii) {
                float e = __expf((Lr[ii] - mx)*SCL);
                ssum += e;
                Lu[row*LST + ii] = tf32c(e);
            }
            ssum += __shfl_xor_sync(0xffffffffu, ssum, 1);
            ssum += __shfl_xor_sync(0xffffffffu, ssum, 2);
            if (qq == 0) inv[row] = 1.0f / ssum;
        }
        __syncthreads();
        for (int idx = tid; idx < 4096; idx += 256) {
            int jj = idx >> 6, d = idx & 63;
            Vs[jj*72 + d] = tf32c(Vg[(size_t)(j0 + jj)*DK + d] * inv[jj]);
        }
        __syncthreads();
        // ---- phase 3: acc_o += P^T V ----
#pragma unroll
        for (int kk8 = 0; kk8 < 8; ++kk8) {
            unsigned a[7][4], b[4][2];
#pragma unroll
            for (int mt = 0; mt < 7; ++mt) {
                a[mt][0] = Lu[(kk8*8+q)*LST   + ibw3 + mt*16 + g];
                a[mt][1] = Lu[(kk8*8+q)*LST   + ibw3 + mt*16 + g + 8];
                a[mt][2] = Lu[(kk8*8+q+4)*LST + ibw3 + mt*16 + g];
                a[mt][3] = Lu[(kk8*8+q+4)*LST + ibw3 + mt*16 + g + 8];
            }
#pragma unroll
            for (int nt = 0; nt < 4; ++nt) {
                b[nt][0] = Vs[(kk8*8+q)*72   + dbw + nt*8 + g];
                b[nt][1] = Vs[(kk8*8+q+4)*72 + dbw + nt*8 + g];
            }
#pragma unroll
            for (int mt = 0; mt < 7; ++mt)
#pragma unroll
            for (int nt = 0; nt < 4; ++nt) mma8(acc_o[mt][nt], a[mt], b[nt]);
        }
        __syncthreads();
    }
#pragma unroll
    for (int nt = 0; nt < 4; ++nt) {
        int d = dbw + nt*8 + 2*q;
#pragma unroll
        for (int mt = 0; mt < 7; ++mt) {
            int i = ibw3 + mt*16 + g;
            size_t o0 = ((size_t)(bb*HWL + i))*CC + hh*DK + d;
            size_t o1 = ((size_t)(bb*HWL + i + 8))*CC + hh*DK + d;
            *(float2*)(g_r + o0) = make_float2(acc_o[mt][nt][0], acc_o[mt][nt][1]);
            *(float2*)(g_r + o1) = make_float2(acc_o[mt][nt][2], acc_o[mt][nt][3]);
        }
    }
}

// ================= K5: out projection + residual (double-buffered) ===========
#define OP_SMEM ((2*32*136 + 2*128*36)*4)
__global__ void __launch_bounds__(256) outproj_kernel(const float* __restrict__ x,
                                                      const float* __restrict__ Wo,
                                                      const float* __restrict__ bo,
                                                      float* __restrict__ out) {
    extern __shared__ unsigned smu[];
    unsigned* As0 = smu;
    unsigned* Bs0 = smu + 2*32*136;
    int tid = threadIdx.x;
    int bn = blockIdx.x, bm = blockIdx.y;
    int wid = tid >> 5, lane = tid & 31, g = lane >> 2, q = lane & 3;
    int cbw = (wid & 1)*64, nbw = (wid >> 1)*32;

    float acc[4][4][4];
#pragma unroll
    for (int mt = 0; mt < 4; ++mt)
#pragma unroll
    for (int nt = 0; nt < 4; ++nt)
#pragma unroll
    for (int r = 0; r < 4; ++r) acc[mt][nt][r] = 0.f;

#define OP_STAGE(kt, buf)                                                        \
    {                                                                            \
        unsigned* A = As0 + (buf)*32*136;                                        \
        unsigned* B = Bs0 + (buf)*128*36;                                        \
        _Pragma("unroll")                                                        \
        for (int r = 0; r < 4; ++r) {                                            \
            int fid = r*256 + tid;                                               \
            int kk = fid >> 5, c4 = (fid & 31)*4;                                \
            cpa16(&A[kk*136 + c4], Wo + (size_t)((kt)*32 + kk)*CC + bm*128 + c4);\
            int n = fid >> 3, k4 = (fid & 7)*4;                                  \
            cpa16(&B[n*36 + k4], g_r + (size_t)(bn*128 + n)*CC + (kt)*32 + k4);  \
        }                                                                        \
        CP_COMMIT();                                                             \
    }

    OP_STAGE(0, 0);
    for (int kt = 0; kt < 16; ++kt) {
        if (kt < 15) { OP_STAGE(kt+1, (kt+1)&1); CP_WAIT(1); }
        else         { CP_WAIT(0); }
        __syncthreads();
        unsigned* As = As0 + (kt&1)*32*136;
        unsigned* Bs = Bs0 + (kt&1)*128*36;
#pragma unroll
        for (int kk8 = 0; kk8 < 4; ++kk8) {
            unsigned a[4][4], b[4][2];
#pragma unroll
            for (int mt = 0; mt < 4; ++mt) {
                a[mt][0] = rnd(As[(kk8*8+q)*136   + cbw + mt*16 + g]);
                a[mt][1] = rnd(As[(kk8*8+q)*136   + cbw + mt*16 + g + 8]);
                a[mt][2] = rnd(As[(kk8*8+q+4)*136 + cbw + mt*16 + g]);
                a[mt][3] = rnd(As[(kk8*8+q+4)*136 + cbw + mt*16 + g + 8]);
            }
#pragma unroll
            for (int nt = 0; nt < 4; ++nt) {
                b[nt][0] = rnd(Bs[(nbw + nt*8 + g)*36 + kk8*8 + q]);
                b[nt][1] = rnd(Bs[(nbw + nt*8 + g)*36 + kk8*8 + q + 4]);
            }
#pragma unroll
            for (int mt = 0; mt < 4; ++mt)
#pragma unroll
            for (int nt = 0; nt < 4; ++nt) mma8(acc[mt][nt], a[mt], b[nt]);
        }
        __syncthreads();
    }
#pragma unroll
    for (int nt = 0; nt < 4; ++nt) {
        int m = bn*128 + nbw + nt*8 + 2*q;
        int b = m / HWL, t = m % HWL;
#pragma unroll
        for (int mt = 0; mt < 4; ++mt) {
            int c0 = bm*128 + cbw + mt*16 + g;
            float bias0 = bo[c0], bias1 = bo[c0 + 8];
            size_t o0 = (size_t)b*CC*HWL + (size_t)c0*HWL + t;
            size_t o1 = o0 + (size_t)8*HWL;
            float2 x0 = *(const float2*)(x + o0);
            float2 x1 = *(const float2*)(x + o1);
            *(float2*)(out + o0) = make_float2(acc[mt][nt][0] + bias0 + x0.x,
                                               acc[mt][nt][1] + bias0 + x0.y);
            *(float2*)(out + o1) = make_float2(acc[mt][nt][2] + bias1 + x1.x,
                                               acc[mt][nt][3] + bias1 + x1.y);
        }
    }
}

extern "C" void kernel_launch(void* const* d_in, const int* in_sizes, int n_in,
                              void* d_out, int out_size) {
    const float* x   = (const float*)d_in[0];
    const float* s   = (const float*)d_in[1];
    const float* Wkv = (const float*)d_in[2];
    const float* bkv = (const float*)d_in[3];
    const float* Wq  = (const float*)d_in[4];
    const float* bq  = (const float*)d_in[5];
    const float* Wo  = (const float*)d_in[6];
    const float* bo  = (const float*)d_in[7];
    float* out = (float*)d_out;

    cudaFuncSetAttribute(qproj_kernel,   cudaFuncAttributeMaxDynamicSharedMemorySize, QP_SMEM);
    cudaFuncSetAttribute(kvproj_kernel,  cudaFuncAttributeMaxDynamicSharedMemorySize, KV_SMEM);
    cudaFuncSetAttribute(attn_kernel,    cudaFuncAttributeMaxDynamicSharedMemorySize, ATTN_SMEM);
    cudaFuncSetAttribute(outproj_kernel, cudaFuncAttributeMaxDynamicSharedMemorySize, OP_SMEM);

    qproj_kernel<<<NQC/256, 256, QP_SMEM>>>(s, Wq, bq);
    kvproj_kernel<<<dim3(8, 112), 256, KV_SMEM>>>(x, Wkv, bkv);
    attn_kernel<<<256, 256, ATTN_SMEM>>>();
    outproj_kernel<<<dim3(112, 4), 256, OP_SMEM>>>(x, Wo, bo, out);
}

// round 8
// speedup vs baseline: 3.2937x; 1.0618x over previous
#include <cuda_runtime.h>

#define BB   32
#define CC   512
#define HWL  448
#define NH   8
#define DK   64
#define NQC  229376
#define SCL  0.125f
#define BHD  (BB*NH*HWL*DK)

__device__ float g_q [BHD];
__device__ float g_k [BHD];
__device__ float g_v [BHD];
__device__ float g_r [BB*HWL*CC];

__device__ __forceinline__ unsigned tf32c(float f) {
    unsigned u; asm("cvt.rna.tf32.f32 %0,%1;" : "=r"(u) : "f"(f)); return u;
}
// round-to-nearest for raw fp32 bits feeding tf32 MMA (HW truncates low 13)
__device__ __forceinline__ unsigned rnd(unsigned u) { return u + 0x1000u; }

__device__ __forceinline__ void mma8(float* c, const unsigned* a, const unsigned* b) {
    asm("mma.sync.aligned.m16n8k8.row.col.f32.tf32.tf32.f32 "
        "{%0,%1,%2,%3},{%4,%5,%6,%7},{%8,%9},{%0,%1,%2,%3};"
        : "+f"(c[0]), "+f"(c[1]), "+f"(c[2]), "+f"(c[3])
        : "r"(a[0]), "r"(a[1]), "r"(a[2]), "r"(a[3]), "r"(b[0]), "r"(b[1]));
}
__device__ __forceinline__ void cpa16(void* sm, const void* gm) {
    unsigned sa = (unsigned)__cvta_generic_to_shared(sm);
    asm volatile("cp.async.cg.shared.global [%0],[%1],16;" :: "r"(sa), "l"(gm));
}
#define CP_COMMIT() asm volatile("cp.async.commit_group;")
#define CP_WAIT(n)  asm volatile("cp.async.wait_group %0;" :: "n"(n))

// ================= K1: q projection (double-buffered) ========================
#define QP_SMEM ((512*40 + 2*64*264)*4)
__global__ void __launch_bounds__(256) qproj_kernel(const float* __restrict__ s,
                                                    const float* __restrict__ Wq,
                                                    const float* __restrict__ bq) {
    extern __shared__ unsigned smu[];
    unsigned* As  = smu;             // [512][40] tf32 (rna), [c][b]
    unsigned* Bs0 = As + 512*40;     // 2 x [64][264] raw fp32 bits
    int tid = threadIdx.x;
    int n0 = blockIdx.x * 256;
    int wid = tid >> 5, lane = tid & 31, g = lane >> 2, q = lane & 3;
    int nb = wid * 32;

    for (int idx = tid; idx < BB*CC; idx += 256) {
        int b = idx >> 9, c = idx & 511;
        As[c*40 + b] = tf32c(s[b*CC + c]);
    }
    {
        unsigned* B = Bs0;
#pragma unroll
        for (int r = 0; r < 16; ++r) {
            int fid = r*256 + tid;
            int kk = fid >> 6, ch = (fid & 63)*4;
            cpa16(&B[kk*264 + ch], Wq + (size_t)kk*NQC + n0 + ch);
        }
        CP_COMMIT();
    }
    float acc[2][4][4];
#pragma unroll
    for (int mt = 0; mt < 2; ++mt)
#pragma unroll
    for (int nt = 0; nt < 4; ++nt)
#pragma unroll
    for (int r = 0; r < 4; ++r) acc[mt][nt][r] = 0.f;

    for (int kt = 0; kt < 8; ++kt) {
        if (kt < 7) {
            unsigned* B = Bs0 + ((kt+1)&1)*64*264;
#pragma unroll
            for (int r = 0; r < 16; ++r) {
                int fid = r*256 + tid;
                int kk = fid >> 6, ch = (fid & 63)*4;
                cpa16(&B[kk*264 + ch], Wq + (size_t)((kt+1)*64 + kk)*NQC + n0 + ch);
            }
            CP_COMMIT();
            CP_WAIT(1);
        } else {
            CP_WAIT(0);
        }
        __syncthreads();
        unsigned* Bs = Bs0 + (kt&1)*64*264;
#pragma unroll
        for (int kk8 = 0; kk8 < 8; ++kk8) {
            int kA = kt*64 + kk8*8;
            unsigned a[2][4], b[4][2];
#pragma unroll
            for (int mt = 0; mt < 2; ++mt) {
                a[mt][0] = As[(kA+q)*40   + mt*16 + g];
                a[mt][1] = As[(kA+q)*40   + mt*16 + g + 8];
                a[mt][2] = As[(kA+q+4)*40 + mt*16 + g];
                a[mt][3] = As[(kA+q+4)*40 + mt*16 + g + 8];
            }
#pragma unroll
            for (int nt = 0; nt < 4; ++nt) {
                b[nt][0] = rnd(Bs[(kk8*8+q)*264   + nb + nt*8 + g]);
                b[nt][1] = rnd(Bs[(kk8*8+q+4)*264 + nb + nt*8 + g]);
            }
#pragma unroll
            for (int mt = 0; mt < 2; ++mt)
#pragma unroll
            for (int nt = 0; nt < 4; ++nt) mma8(acc[mt][nt], a[mt], b[nt]);
        }
        __syncthreads();
    }
#pragma unroll
    for (int nt = 0; nt < 4; ++nt) {
        int j = n0 + nb + nt*8 + 2*q;
        int i = j >> 9, hd = j & 511, h = hd >> 6, d = hd & 63;
        float b0f = bq[j], b1f = bq[j+1];
#pragma unroll
        for (int mt = 0; mt < 2; ++mt) {
            int br = mt*16 + g;
            float* d0 = g_q + ((size_t)((br*NH + h)*HWL + i))*DK + d;
            float* d1 = g_q + ((size_t)(((br+8)*NH + h)*HWL + i))*DK + d;
            *(float2*)d0 = make_float2(acc[mt][nt][0] + b0f, acc[mt][nt][1] + b1f);
            *(float2*)d1 = make_float2(acc[mt][nt][2] + b0f, acc[mt][nt][3] + b1f);
        }
    }
}

// ================= K2: kv projection (double-buffered) =======================
#define KV_SMEM (4*32*136*4)
__global__ void __launch_bounds__(256) kvproj_kernel(const float* __restrict__ x,
                                                     const float* __restrict__ Wkv,
                                                     const float* __restrict__ bkv) {
    extern __shared__ unsigned smu[];
    unsigned* As0 = smu;
    unsigned* Bs0 = smu + 2*32*136;
    int tid = threadIdx.x;
    int bn = blockIdx.x, bm = blockIdx.y;
    int wid = tid >> 5, lane = tid & 31, g = lane >> 2, q = lane & 3;
    int mbw = (wid & 1)*64, nbw = (wid >> 1)*32;

    float acc[4][4][4];
#pragma unroll
    for (int mt = 0; mt < 4; ++mt)
#pragma unroll
    for (int nt = 0; nt < 4; ++nt)
#pragma unroll
    for (int r = 0; r < 4; ++r) acc[mt][nt][r] = 0.f;

#define KV_STAGE(kt, buf)                                                       \
    {                                                                           \
        unsigned* A = As0 + (buf)*32*136;                                       \
        unsigned* B = Bs0 + (buf)*32*136;                                       \
        _Pragma("unroll")                                                       \
        for (int r = 0; r < 4; ++r) {                                           \
            int fid = r*256 + tid;                                              \
            int kk = fid >> 5, m4 = (fid & 31)*4;                               \
            int m = bm*128 + m4;                                                \
            int ab = m / HWL, at = m % HWL;                                     \
            cpa16(&A[kk*136 + m4], x + ((size_t)(ab*CC + (kt)*32 + kk))*HWL + at); \
            cpa16(&B[kk*136 + m4], Wkv + (size_t)((kt)*32 + kk)*1024 + bn*128 + m4); \
        }                                                                       \
        CP_COMMIT();                                                            \
    }

    KV_STAGE(0, 0);
    for (int kt = 0; kt < 16; ++kt) {
        if (kt < 15) { KV_STAGE(kt+1, (kt+1)&1); CP_WAIT(1); }
        else         { CP_WAIT(0); }
        __syncthreads();
        unsigned* As = As0 + (kt&1)*32*136;
        unsigned* Bs = Bs0 + (kt&1)*32*136;
#pragma unroll
        for (int kk8 = 0; kk8 < 4; ++kk8) {
            unsigned a[4][4], b[4][2];
#pragma unroll
            for (int mt = 0; mt < 4; ++mt) {
                a[mt][0] = rnd(As[(kk8*8+q)*136   + mbw + mt*16 + g]);
                a[mt][1] = rnd(As[(kk8*8+q)*136   + mbw + mt*16 + g + 8]);
                a[mt][2] = rnd(As[(kk8*8+q+4)*136 + mbw + mt*16 + g]);
                a[mt][3] = rnd(As[(kk8*8+q+4)*136 + mbw + mt*16 + g + 8]);
            }
#pragma unroll
            for (int nt = 0; nt < 4; ++nt) {
                b[nt][0] = rnd(Bs[(kk8*8+q)*136   + nbw + nt*8 + g]);
                b[nt][1] = rnd(Bs[(kk8*8+q+4)*136 + nbw + nt*8 + g]);
            }
#pragma unroll
            for (int mt = 0; mt < 4; ++mt)
#pragma unroll
            for (int nt = 0; nt < 4; ++nt) mma8(acc[mt][nt], a[mt], b[nt]);
        }
        __syncthreads();
    }
#pragma unroll
    for (int nt = 0; nt < 4; ++nt) {
        int n = nbw + nt*8 + 2*q;
        float b0f = bkv[bn*128 + n], b1f = bkv[bn*128 + n + 1];
        int d = n & 63;
        float* base = (n < 64) ? g_k : g_v;
#pragma unroll
        for (int mt = 0; mt < 4; ++mt) {
            int m = bm*128 + mbw + mt*16 + g;
            int b0 = m / HWL, t0 = m % HWL;
            int m1 = m + 8;
            int b1 = m1 / HWL, t1 = m1 % HWL;
            *(float2*)(base + ((size_t)((b0*NH + bn)*HWL + t0))*DK + d) =
                make_float2(acc[mt][nt][0] + b0f, acc[mt][nt][1] + b1f);
            *(float2*)(base + ((size_t)((b1*NH + bn)*HWL + t1))*DK + d) =
                make_float2(acc[mt][nt][2] + b0f, acc[mt][nt][3] + b1f);
        }
    }
}

// ================= K3: merged fused attention per (b,h) ======================
#define LST 456
#define ATTN_SMEM ((64*68 + 224*72 + 64*72 + 64*LST + 64)*4)
__global__ void __launch_bounds__(256) attn_kernel() {
    extern __shared__ unsigned smu[];
    unsigned* Ks = smu;                    // [j][d] stride 68 (raw)
    unsigned* Qs = Ks + 64*68;             // [i][d] stride 72 (224 rows)
    unsigned* Vs = Qs + 224*72;            // [j][d] stride 72 (raw -> tf32*inv in place)
    float*    Lsm = (float*)(Vs + 64*72);  // [j][i] stride 456
    float*    inv = Lsm + 64*LST;
    unsigned* Lu = (unsigned*)Lsm;

    int tid = threadIdx.x;
    int bh = blockIdx.x;
    const float* Kg = g_k + (size_t)bh*HWL*DK;
    const float* Qg = g_q + (size_t)bh*HWL*DK;
    const float* Vg = g_v + (size_t)bh*HWL*DK;
    int wid = tid >> 5, lane = tid & 31, g = lane >> 2, q = lane & 3;
    int jbw = (wid & 1)*32, ibw = (wid >> 1)*56;
    int ibw3 = (wid & 3)*112, dbw = (wid >> 2)*32;
    int bb = bh >> 3, hh = bh & 7;

    float acc_o[7][4][4];
#pragma unroll
    for (int mt = 0; mt < 7; ++mt)
#pragma unroll
    for (int nt = 0; nt < 4; ++nt)
#pragma unroll
    for (int r = 0; r < 4; ++r) acc_o[mt][nt][r] = 0.f;

    // prologue: stage K(0)
    {
#pragma unroll
        for (int r = 0; r < 4; ++r) {
            int fid = r*256 + tid;
            int jj = fid >> 4, ch = (fid & 15)*4;
            cpa16(&Ks[jj*68 + ch], Kg + (size_t)jj*DK + ch);
        }
        CP_COMMIT();
    }

    for (int jb = 0; jb < 7; ++jb) {
        int j0 = jb*64;
        // stage V(jb) raw (hidden under phase 1)
        {
#pragma unroll
            for (int r = 0; r < 4; ++r) {
                int fid = r*256 + tid;
                int jj = fid >> 4, ch = (fid & 15)*4;
                cpa16(&Vs[jj*72 + ch], Vg + (size_t)(j0 + jj)*DK + ch);
            }
            CP_COMMIT();
        }
        // ---- phase 1: logits over two i-halves ----
        for (int ih = 0; ih < 2; ++ih) {
#pragma unroll
            for (int r = 0; r < 14; ++r) {
                int fid = r*256 + tid;
                int ii = fid >> 4, ch = (fid & 15)*4;
                cpa16(&Qs[ii*72 + ch], Qg + (size_t)(ih*224 + ii)*DK + ch);
            }
            CP_COMMIT();
            CP_WAIT(0);
            __syncthreads();

            // nt split into chunks of 4 + 3 to cap live registers
#pragma unroll
            for (int ntc = 0; ntc < 2; ++ntc) {
                const int NTN = ntc ? 3 : 4;
                float a1[4][2][4];
#pragma unroll
                for (int nt = 0; nt < 4; ++nt)
#pragma unroll
                for (int mt = 0; mt < 2; ++mt)
#pragma unroll
                for (int r = 0; r < 4; ++r) a1[nt][mt][r] = 0.f;
#pragma unroll
                for (int kk8 = 0; kk8 < 8; ++kk8) {
                    unsigned a[2][4], b[4][2];
#pragma unroll
                    for (int mt = 0; mt < 2; ++mt) {
                        a[mt][0] = rnd(Ks[(jbw + mt*16 + g)*68     + kk8*8 + q]);
                        a[mt][1] = rnd(Ks[(jbw + mt*16 + g + 8)*68 + kk8*8 + q]);
                        a[mt][2] = rnd(Ks[(jbw + mt*16 + g)*68     + kk8*8 + q + 4]);
                        a[mt][3] = rnd(Ks[(jbw + mt*16 + g + 8)*68 + kk8*8 + q + 4]);
                    }
#pragma unroll
                    for (int nt = 0; nt < NTN; ++nt) {
                        int ntg = ntc*4 + nt;
                        b[nt][0] = rnd(Qs[(ibw + ntg*8 + g)*72 + kk8*8 + q]);
                        b[nt][1] = rnd(Qs[(ibw + ntg*8 + g)*72 + kk8*8 + q + 4]);
                    }
#pragma unroll
                    for (int mt = 0; mt < 2; ++mt)
#pragma unroll
                    for (int nt = 0; nt < NTN; ++nt) mma8(a1[nt][mt], a[mt], b[nt]);
                }
#pragma unroll
                for (int nt = 0; nt < NTN; ++nt) {
                    int i = ih*224 + ibw + (ntc*4 + nt)*8 + 2*q;
#pragma unroll
                    for (int mt = 0; mt < 2; ++mt) {
                        int jr = jbw + mt*16 + g;
                        *(float2*)&Lsm[jr*LST + i]     = make_float2(a1[nt][mt][0], a1[nt][mt][1]);
                        *(float2*)&Lsm[(jr+8)*LST + i] = make_float2(a1[nt][mt][2], a1[nt][mt][3]);
                    }
                }
            }
            __syncthreads();
        }
        // prefetch K(jb+1) — lands during softmax/phase3
        if (jb < 6) {
#pragma unroll
            for (int r = 0; r < 4; ++r) {
                int fid = r*256 + tid;
                int jj = fid >> 4, ch = (fid & 15)*4;
                cpa16(&Ks[jj*68 + ch], Kg + (size_t)(j0 + 64 + jj)*DK + ch);
            }
            CP_COMMIT();
        }
        // ---- phase 2: softmax over i per j-row (SCL folded), store tf32 ----
        {
            int row = tid >> 2, qq = tid & 3;
            float* Lr = Lsm + row*LST;
            float mx = -1e30f;
            for (int ii = qq*112; ii < qq*112 + 112; ++ii) mx = fmaxf(mx, Lr[ii]);
            mx = fmaxf(mx, __shfl_xor_sync(0xffffffffu, mx, 1));
            mx = fmaxf(mx, __shfl_xor_sync(0xffffffffu, mx, 2));
            float ssum = 0.f;
            for (int ii = qq*112; ii < qq*112 + 112; ++ii) {
                float e = __expf((Lr[ii] - mx)*SCL);
                ssum += e;
                Lu[row*LST + ii] = tf32c(e);
            }
            ssum += __shfl_xor_sync(0xffffffffu, ssum, 1);
            ssum += __shfl_xor_sync(0xffffffffu, ssum, 2);
            if (qq == 0) inv[row] = 1.0f / ssum;
        }
        __syncthreads();
        // V normalize in place (smem -> smem, tf32)
#pragma unroll
        for (int r = 0; r < 16; ++r) {
            int idx = tid + r*256;
            int jj = idx >> 6, d = idx & 63;
            float v = __uint_as_float(Vs[jj*72 + d]) * inv[jj];
            Vs[jj*72 + d] = tf32c(v);
        }
        __syncthreads();
        // ---- phase 3: acc_o += P^T V ----
#pragma unroll
        for (int kk8 = 0; kk8 < 8; ++kk8) {
            unsigned a[7][4], b[4][2];
#pragma unroll
            for (int mt = 0; mt < 7; ++mt) {
                a[mt][0] = Lu[(kk8*8+q)*LST   + ibw3 + mt*16 + g];
                a[mt][1] = Lu[(kk8*8+q)*LST   + ibw3 + mt*16 + g + 8];
                a[mt][2] = Lu[(kk8*8+q+4)*LST + ibw3 + mt*16 + g];
                a[mt][3] = Lu[(kk8*8+q+4)*LST + ibw3 + mt*16 + g + 8];
            }
#pragma unroll
            for (int nt = 0; nt < 4; ++nt) {
                b[nt][0] = Vs[(kk8*8+q)*72   + dbw + nt*8 + g];
                b[nt][1] = Vs[(kk8*8+q+4)*72 + dbw + nt*8 + g];
            }
#pragma unroll
            for (int mt = 0; mt < 7; ++mt)
#pragma unroll
            for (int nt = 0; nt < 4; ++nt) mma8(acc_o[mt][nt], a[mt], b[nt]);
        }
        __syncthreads();
    }
#pragma unroll
    for (int nt = 0; nt < 4; ++nt) {
        int d = dbw + nt*8 + 2*q;
#pragma unroll
        for (int mt = 0; mt < 7; ++mt) {
            int i = ibw3 + mt*16 + g;
            size_t o0 = ((size_t)(bb*HWL + i))*CC + hh*DK + d;
            size_t o1 = ((size_t)(bb*HWL + i + 8))*CC + hh*DK + d;
            *(float2*)(g_r + o0) = make_float2(acc_o[mt][nt][0], acc_o[mt][nt][1]);
            *(float2*)(g_r + o1) = make_float2(acc_o[mt][nt][2], acc_o[mt][nt][3]);
        }
    }
}

// ================= K5: out projection + residual (double-buffered) ===========
#define OP_SMEM ((2*32*136 + 2*128*36)*4)
__global__ void __launch_bounds__(256) outproj_kernel(const float* __restrict__ x,
                                                      const float* __restrict__ Wo,
                                                      const float* __restrict__ bo,
                                                      float* __restrict__ out) {
    extern __shared__ unsigned smu[];
    unsigned* As0 = smu;
    unsigned* Bs0 = smu + 2*32*136;
    int tid = threadIdx.x;
    int bn = blockIdx.x, bm = blockIdx.y;
    int wid = tid >> 5, lane = tid & 31, g = lane >> 2, q = lane & 3;
    int cbw = (wid & 1)*64, nbw = (wid >> 1)*32;

    float acc[4][4][4];
#pragma unroll
    for (int mt = 0; mt < 4; ++mt)
#pragma unroll
    for (int nt = 0; nt < 4; ++nt)
#pragma unroll
    for (int r = 0; r < 4; ++r) acc[mt][nt][r] = 0.f;

#define OP_STAGE(kt, buf)                                                        \
    {                                                                            \
        unsigned* A = As0 + (buf)*32*136;                                        \
        unsigned* B = Bs0 + (buf)*128*36;                                        \
        _Pragma("unroll")                                                        \
        for (int r = 0; r < 4; ++r) {                                            \
            int fid = r*256 + tid;                                               \
            int kk = fid >> 5, c4 = (fid & 31)*4;                                \
            cpa16(&A[kk*136 + c4], Wo + (size_t)((kt)*32 + kk)*CC + bm*128 + c4);\
            int n = fid >> 3, k4 = (fid & 7)*4;                                  \
            cpa16(&B[n*36 + k4], g_r + (size_t)(bn*128 + n)*CC + (kt)*32 + k4);  \
        }                                                                        \
        CP_COMMIT();                                                             \
    }

    OP_STAGE(0, 0);
    for (int kt = 0; kt < 16; ++kt) {
        if (kt < 15) { OP_STAGE(kt+1, (kt+1)&1); CP_WAIT(1); }
        else         { CP_WAIT(0); }
        __syncthreads();
        unsigned* As = As0 + (kt&1)*32*136;
        unsigned* Bs = Bs0 + (kt&1)*128*36;
#pragma unroll
        for (int kk8 = 0; kk8 < 4; ++kk8) {
            unsigned a[4][4], b[4][2];
#pragma unroll
            for (int mt = 0; mt < 4; ++mt) {
                a[mt][0] = rnd(As[(kk8*8+q)*136   + cbw + mt*16 + g]);
                a[mt][1] = rnd(As[(kk8*8+q)*136   + cbw + mt*16 + g + 8]);
                a[mt][2] = rnd(As[(kk8*8+q+4)*136 + cbw + mt*16 + g]);
                a[mt][3] = rnd(As[(kk8*8+q+4)*136 + cbw + mt*16 + g + 8]);
            }
#pragma unroll
            for (int nt = 0; nt < 4; ++nt) {
                b[nt][0] = rnd(Bs[(nbw + nt*8 + g)*36 + kk8*8 + q]);
                b[nt][1] = rnd(Bs[(nbw + nt*8 + g)*36 + kk8*8 + q + 4]);
            }
#pragma unroll
            for (int mt = 0; mt < 4; ++mt)
#pragma unroll
            for (int nt = 0; nt < 4; ++nt) mma8(acc[mt][nt], a[mt], b[nt]);
        }
        __syncthreads();
    }
#pragma unroll
    for (int nt = 0; nt < 4; ++nt) {
        int m = bn*128 + nbw + nt*8 + 2*q;
        int b = m / HWL, t = m % HWL;
#pragma unroll
        for (int mt = 0; mt < 4; ++mt) {
            int c0 = bm*128 + cbw + mt*16 + g;
            float bias0 = bo[c0], bias1 = bo[c0 + 8];
            size_t o0 = (size_t)b*CC*HWL + (size_t)c0*HWL + t;
            size_t o1 = o0 + (size_t)8*HWL;
            float2 x0 = *(const float2*)(x + o0);
            float2 x1 = *(const float2*)(x + o1);
            *(float2*)(out + o0) = make_float2(acc[mt][nt][0] + bias0 + x0.x,
                                               acc[mt][nt][1] + bias0 + x0.y);
            *(float2*)(out + o1) = make_float2(acc[mt][nt][2] + bias1 + x1.x,
                                               acc[mt][nt][3] + bias1 + x1.y);
        }
    }
}

extern "C" void kernel_launch(void* const* d_in, const int* in_sizes, int n_in,
                              void* d_out, int out_size) {
    const float* x   = (const float*)d_in[0];
    const float* s   = (const float*)d_in[1];
    const float* Wkv = (const float*)d_in[2];
    const float* bkv = (const float*)d_in[3];
    const float* Wq  = (const float*)d_in[4];
    const float* bq  = (const float*)d_in[5];
    const float* Wo  = (const float*)d_in[6];
    const float* bo  = (const float*)d_in[7];
    float* out = (float*)d_out;

    // lazily-created aux stream + events for the qproj || kvproj fork
    static cudaStream_t s_aux = 0;
    static cudaEvent_t  e_fork = 0, e_join = 0;
    if (!s_aux) {
        cudaStreamCreateWithFlags(&s_aux, cudaStreamNonBlocking);
        cudaEventCreateWithFlags(&e_fork, cudaEventDisableTiming);
        cudaEventCreateWithFlags(&e_join, cudaEventDisableTiming);
    }

    cudaFuncSetAttribute(qproj_kernel,   cudaFuncAttributeMaxDynamicSharedMemorySize, QP_SMEM);
    cudaFuncSetAttribute(kvproj_kernel,  cudaFuncAttributeMaxDynamicSharedMemorySize, KV_SMEM);
    cudaFuncSetAttribute(attn_kernel,    cudaFuncAttributeMaxDynamicSharedMemorySize, ATTN_SMEM);
    cudaFuncSetAttribute(outproj_kernel, cudaFuncAttributeMaxDynamicSharedMemorySize, OP_SMEM);

    cudaEventRecord(e_fork, 0);
    cudaStreamWaitEvent(s_aux, e_fork, 0);
    kvproj_kernel<<<dim3(8, 112), 256, KV_SMEM, s_aux>>>(x, Wkv, bkv);
    cudaEventRecord(e_join, s_aux);

    qproj_kernel<<<NQC/256, 256, QP_SMEM>>>(s, Wq, bq);

    cudaStreamWaitEvent(0, e_join, 0);
    attn_kernel<<<256, 256, ATTN_SMEM>>>();
    outproj_kernel<<<dim3(112, 4), 256, OP_SMEM>>>(x, Wo, bo, out);
}